// round 15
// baseline (speedup 1.0000x reference)
#include <cuda_runtime.h>
#include <cuda_fp16.h>

#define N_NODES 100000
#define F0 256
#define F1 128
#define F2 64
#define MAX_E 1600000
#define NB 391   // ceil(N_NODES/256)

// Scratch (allocation-free rule: __device__ globals). 16B-aligned for vector access.
__device__ int   g_is_i32 = 0;       // sticky: same input -> same value every call
__device__ int   g_deg[N_NODES];     // zero at load; re-zeroed by gather2 each call
__device__ float g_dinv[N_NODES];
__device__ int   g_row32[MAX_E];
__device__ int   g_col32[MAX_E];
__device__ int   g_csr[MAX_E];
__device__ int   g_pref[N_NODES];
__device__ int   g_bsum[NB];
__device__ int   g_boff[NB];
__device__ int   g_rowptr[N_NODES];
__device__ int   g_fill[N_NODES];
__device__ __align__(16) __half g_h1[N_NODES * F1];  // dinv-scaled x@W1 (fp16)
__device__ __align__(16) __half g_y1[N_NODES * F1];  // relu output (fp16)
__device__ __align__(16) __half g_h2[N_NODES * F2];  // dinv-scaled (y1@W2) (fp16)

// ---------------- tf32 helpers (measured-good mma config) ----------------

__device__ __forceinline__ unsigned f2tf32(float f) {
    unsigned u;
    asm("cvt.rna.tf32.f32 %0, %1;" : "=r"(u) : "f"(f));
    return u;
}

__device__ __forceinline__ void mma_tf32(float* c, const unsigned* a, const unsigned* b) {
    asm volatile(
        "mma.sync.aligned.m16n8k8.row.col.f32.tf32.tf32.f32 "
        "{%0,%1,%2,%3}, {%4,%5,%6,%7}, {%8,%9}, {%0,%1,%2,%3};\n"
        : "+f"(c[0]), "+f"(c[1]), "+f"(c[2]), "+f"(c[3])
        : "r"(a[0]), "r"(a[1]), "r"(a[2]), "r"(a[3]), "r"(b[0]), "r"(b[1]));
}

// ---------------- dtype detection (1 block; g_deg zeroed by prior gather2) ----------------

__global__ void k_detect(const long long* __restrict__ ei) {
    long long v = ei[threadIdx.x];
    if (v < 0 || v >= N_NODES) g_is_i32 = 1;   // sticky, deterministic
}

__global__ void k_prep_edges(const void* __restrict__ eiv, int E) {
    int e = blockIdx.x * blockDim.x + threadIdx.x;
    if (e >= E) return;
    int r, c;
    if (g_is_i32) {
        const int* p = (const int*)eiv;
        r = p[e]; c = p[E + e];
    } else {
        const long long* p = (const long long*)eiv;
        r = (int)p[e]; c = (int)p[E + e];
    }
    r = min(max(r, 0), N_NODES - 1);
    c = min(max(c, 0), N_NODES - 1);
    g_row32[e] = r;
    g_col32[e] = c;
    atomicAdd(&g_deg[c], 1);
}

// ---------------- CSR build (dinv fused into block scan) ----------------

__global__ void k_scan_block() {
    __shared__ int s[256];
    int tid = threadIdx.x;
    int i = blockIdx.x * 256 + tid;
    int v = (i < N_NODES) ? g_deg[i] : 0;
    if (i < N_NODES) g_dinv[i] = rsqrtf((float)(v + 1));
    s[tid] = v;
    __syncthreads();
#pragma unroll
    for (int d = 1; d < 256; d <<= 1) {
        int t = (tid >= d) ? s[tid - d] : 0;
        __syncthreads();
        s[tid] += t;
        __syncthreads();
    }
    if (i < N_NODES) g_pref[i] = s[tid] - v;
    if (tid == 255) g_bsum[blockIdx.x] = s[255];
}

__global__ void k_scan_top() {
    __shared__ int s[512];
    int tid = threadIdx.x;
    int v = (tid < NB) ? g_bsum[tid] : 0;
    s[tid] = v;
    __syncthreads();
#pragma unroll
    for (int d = 1; d < 512; d <<= 1) {
        int t = (tid >= d) ? s[tid - d] : 0;
        __syncthreads();
        s[tid] += t;
        __syncthreads();
    }
    if (tid < NB) g_boff[tid] = s[tid] - v;
}

__global__ void k_scan_add() {
    int i = blockIdx.x * blockDim.x + threadIdx.x;
    if (i < N_NODES) {
        int rp = g_pref[i] + g_boff[i >> 8];
        g_rowptr[i] = rp;
        g_fill[i] = rp;
    }
}

__global__ void k_fill(int E) {
    int e = blockIdx.x * blockDim.x + threadIdx.x;
    if (e >= E) return;
    int c = g_col32[e];
    int pos = atomicAdd(&g_fill[c], 1);
    g_csr[pos] = g_row32[e];
}

// ---------------- GEMM1 (tf32 mma): g_h1 = fp16( (x @ W1) * dinv[row] )
// Block tile 128x128, 8 warps in 4(m) x 2(n), warp tile 32x64.

__global__ void __launch_bounds__(256) k_gemm1(const float* __restrict__ x,
                                               const float* __restrict__ W) {
    __shared__ unsigned As[128][36];
    __shared__ unsigned Bs[32][132];
    int tid = threadIdx.x;
    int lane = tid & 31;
    int wid = tid >> 5;
    int warp_m = wid & 3;
    int warp_n = wid >> 2;
    int grp = lane >> 2;
    int thr = lane & 3;
    int mbase = blockIdx.x * 128;

    float acc[2][8][4];
#pragma unroll
    for (int mf = 0; mf < 2; mf++)
#pragma unroll
        for (int nf = 0; nf < 8; nf++)
#pragma unroll
            for (int q = 0; q < 4; q++) acc[mf][nf][q] = 0.f;

    for (int kt = 0; kt < F0; kt += 32) {
#pragma unroll
        for (int i = 0; i < 4; i++) {
            int idx4 = tid + i * 256;
            int m = idx4 >> 3;
            int kk = (idx4 & 7) * 4;
            int gm = mbase + m;
            float4 v = make_float4(0.f, 0.f, 0.f, 0.f);
            if (gm < N_NODES) v = *(const float4*)(x + gm * F0 + kt + kk);
            uint4 u;
            u.x = f2tf32(v.x); u.y = f2tf32(v.y); u.z = f2tf32(v.z); u.w = f2tf32(v.w);
            *(uint4*)(&As[m][kk]) = u;
        }
#pragma unroll
        for (int i = 0; i < 4; i++) {
            int idx4 = tid + i * 256;
            int k = idx4 >> 5;
            int nn = (idx4 & 31) * 4;
            float4 v = *(const float4*)(W + (kt + k) * F1 + nn);
            uint4 u;
            u.x = f2tf32(v.x); u.y = f2tf32(v.y); u.z = f2tf32(v.z); u.w = f2tf32(v.w);
            *(uint4*)(&Bs[k][nn]) = u;
        }
        __syncthreads();

#pragma unroll
        for (int k0 = 0; k0 < 32; k0 += 8) {
            unsigned a[2][4];
#pragma unroll
            for (int mf = 0; mf < 2; mf++) {
                int r = warp_m * 32 + mf * 16 + grp;
                a[mf][0] = As[r][k0 + thr];
                a[mf][1] = As[r + 8][k0 + thr];
                a[mf][2] = As[r][k0 + 4 + thr];
                a[mf][3] = As[r + 8][k0 + 4 + thr];
            }
            unsigned b[8][2];
#pragma unroll
            for (int nf = 0; nf < 8; nf++) {
                int cNo = warp_n * 64 + nf * 8 + grp;
                b[nf][0] = Bs[k0 + thr][cNo];
                b[nf][1] = Bs[k0 + 4 + thr][cNo];
            }
#pragma unroll
            for (int mf = 0; mf < 2; mf++)
#pragma unroll
                for (int nf = 0; nf < 8; nf++)
                    mma_tf32(acc[mf][nf], a[mf], b[nf]);
        }
        __syncthreads();
    }

#pragma unroll
    for (int mf = 0; mf < 2; mf++) {
        int r0 = mbase + warp_m * 32 + mf * 16 + grp;
        int r1 = r0 + 8;
        float s0 = (r0 < N_NODES) ? g_dinv[r0] : 0.f;
        float s1 = (r1 < N_NODES) ? g_dinv[r1] : 0.f;
#pragma unroll
        for (int nf = 0; nf < 8; nf++) {
            int cNo = warp_n * 64 + nf * 8 + thr * 2;
            if (r0 < N_NODES)
                *(half2*)(g_h1 + r0 * F1 + cNo) =
                    __floats2half2_rn(acc[mf][nf][0] * s0, acc[mf][nf][1] * s0);
            if (r1 < N_NODES)
                *(half2*)(g_h1 + r1 * F1 + cNo) =
                    __floats2half2_rn(acc[mf][nf][2] * s1, acc[mf][nf][3] * s1);
        }
    }
}

// ---------------- Gather layer 1: warp per node, 4-way unroll

__global__ void __launch_bounds__(256) k_gather1(const float* __restrict__ b1) {
    int w = (blockIdx.x * blockDim.x + threadIdx.x) >> 5;
    if (w >= N_NODES) return;
    int lane = threadIdx.x & 31;
    int c = w;
    int fo = lane * 4;

    float2 a0 = __half22float2(*(const half2*)(g_h1 + c * F1 + fo));
    float2 a1 = __half22float2(*(const half2*)(g_h1 + c * F1 + fo + 2));
    float4 acc = make_float4(a0.x, a0.y, a1.x, a1.y);   // self-loop term

    int start = g_rowptr[c];
    int end = start + g_deg[c];

    int j = start;
    for (; j + 4 <= end; j += 4) {
        int i0 = g_csr[j], i1 = g_csr[j + 1], i2 = g_csr[j + 2], i3 = g_csr[j + 3];
        uint2 u0 = *(const uint2*)(g_h1 + i0 * F1 + fo);
        uint2 u1 = *(const uint2*)(g_h1 + i1 * F1 + fo);
        uint2 u2 = *(const uint2*)(g_h1 + i2 * F1 + fo);
        uint2 u3 = *(const uint2*)(g_h1 + i3 * F1 + fo);
        float2 p;
        p = __half22float2(*(half2*)&u0.x); acc.x += p.x; acc.y += p.y;
        p = __half22float2(*(half2*)&u0.y); acc.z += p.x; acc.w += p.y;
        p = __half22float2(*(half2*)&u1.x); acc.x += p.x; acc.y += p.y;
        p = __half22float2(*(half2*)&u1.y); acc.z += p.x; acc.w += p.y;
        p = __half22float2(*(half2*)&u2.x); acc.x += p.x; acc.y += p.y;
        p = __half22float2(*(half2*)&u2.y); acc.z += p.x; acc.w += p.y;
        p = __half22float2(*(half2*)&u3.x); acc.x += p.x; acc.y += p.y;
        p = __half22float2(*(half2*)&u3.y); acc.z += p.x; acc.w += p.y;
    }
    for (; j < end; j++) {
        int i0 = g_csr[j];
        uint2 u0 = *(const uint2*)(g_h1 + i0 * F1 + fo);
        float2 p;
        p = __half22float2(*(half2*)&u0.x); acc.x += p.x; acc.y += p.y;
        p = __half22float2(*(half2*)&u0.y); acc.z += p.x; acc.w += p.y;
    }

    float s = g_dinv[c];
    float4 bb = *(const float4*)(b1 + fo);
    acc.x = fmaxf(fmaf(s, acc.x, bb.x), 0.f);
    acc.y = fmaxf(fmaf(s, acc.y, bb.y), 0.f);
    acc.z = fmaxf(fmaf(s, acc.z, bb.z), 0.f);
    acc.w = fmaxf(fmaf(s, acc.w, bb.w), 0.f);
    *(half2*)(g_y1 + c * F1 + fo)     = __floats2half2_rn(acc.x, acc.y);
    *(half2*)(g_y1 + c * F1 + fo + 2) = __floats2half2_rn(acc.z, acc.w);
}

// ---------------- GEMM2 (tf32 mma): g_h2 = fp16( (y1 @ W2) * dinv[row] )

__global__ void __launch_bounds__(256) k_gemm2(const float* __restrict__ W) {
    __shared__ unsigned As[128][36];
    __shared__ unsigned Bs[32][68];
    int tid = threadIdx.x;
    int lane = tid & 31;
    int wid = tid >> 5;
    int grp = lane >> 2;
    int thr = lane & 3;
    int mbase = blockIdx.x * 128;

    float acc[8][4];
#pragma unroll
    for (int nf = 0; nf < 8; nf++)
#pragma unroll
        for (int q = 0; q < 4; q++) acc[nf][q] = 0.f;

    for (int kt = 0; kt < F1; kt += 32) {
#pragma unroll
        for (int i = 0; i < 4; i++) {
            int idx4 = tid + i * 256;
            int m = idx4 >> 3;
            int kk = (idx4 & 7) * 4;
            int gm = mbase + m;
            float2 p0 = make_float2(0.f, 0.f), p1 = make_float2(0.f, 0.f);
            if (gm < N_NODES) {
                uint2 u = *(const uint2*)(g_y1 + gm * F1 + kt + kk);
                p0 = __half22float2(*(half2*)&u.x);
                p1 = __half22float2(*(half2*)&u.y);
            }
            uint4 t;
            t.x = f2tf32(p0.x); t.y = f2tf32(p0.y); t.z = f2tf32(p1.x); t.w = f2tf32(p1.y);
            *(uint4*)(&As[m][kk]) = t;
        }
#pragma unroll
        for (int i = 0; i < 2; i++) {
            int idx4 = tid + i * 256;
            int k = idx4 >> 4;
            int nn = (idx4 & 15) * 4;
            float4 v = *(const float4*)(W + (kt + k) * F2 + nn);
            uint4 u;
            u.x = f2tf32(v.x); u.y = f2tf32(v.y); u.z = f2tf32(v.z); u.w = f2tf32(v.w);
            *(uint4*)(&Bs[k][nn]) = u;
        }
        __syncthreads();

#pragma unroll
        for (int k0 = 0; k0 < 32; k0 += 8) {
            unsigned a[4];
            int r = wid * 16 + grp;
            a[0] = As[r][k0 + thr];
            a[1] = As[r + 8][k0 + thr];
            a[2] = As[r][k0 + 4 + thr];
            a[3] = As[r + 8][k0 + 4 + thr];
            unsigned b[8][2];
#pragma unroll
            for (int nf = 0; nf < 8; nf++) {
                int cNo = nf * 8 + grp;
                b[nf][0] = Bs[k0 + thr][cNo];
                b[nf][1] = Bs[k0 + 4 + thr][cNo];
            }
#pragma unroll
            for (int nf = 0; nf < 8; nf++)
                mma_tf32(acc[nf], a, b[nf]);
        }
        __syncthreads();
    }

    int r0 = mbase + wid * 16 + grp;
    int r1 = r0 + 8;
    float s0 = (r0 < N_NODES) ? g_dinv[r0] : 0.f;
    float s1 = (r1 < N_NODES) ? g_dinv[r1] : 0.f;
#pragma unroll
    for (int nf = 0; nf < 8; nf++) {
        int cNo = nf * 8 + thr * 2;
        if (r0 < N_NODES)
            *(half2*)(g_h2 + r0 * F2 + cNo) =
                __floats2half2_rn(acc[nf][0] * s0, acc[nf][1] * s0);
        if (r1 < N_NODES)
            *(half2*)(g_h2 + r1 * F2 + cNo) =
                __floats2half2_rn(acc[nf][2] * s1, acc[nf][3] * s1);
    }
}

// ---------------- Gather layer 2: warp per node, 4-way unroll
// Also re-zeroes g_deg[c] for the next call (last consumer of deg).

__global__ void __launch_bounds__(256) k_gather2(float* __restrict__ out,
                                                 const float* __restrict__ b2) {
    int w = (blockIdx.x * blockDim.x + threadIdx.x) >> 5;
    if (w >= N_NODES) return;
    int lane = threadIdx.x & 31;
    int c = w;
    int fo = lane * 2;

    float2 acc = __half22float2(*(const half2*)(g_h2 + c * F2 + fo));
    int start = g_rowptr[c];
    int dg = g_deg[c];
    int end = start + dg;
    if (lane == 0) g_deg[c] = 0;   // reset for next call (only reader is this warp)

    int j = start;
    for (; j + 4 <= end; j += 4) {
        int i0 = g_csr[j], i1 = g_csr[j + 1], i2 = g_csr[j + 2], i3 = g_csr[j + 3];
        float2 v0 = __half22float2(*(const half2*)(g_h2 + i0 * F2 + fo));
        float2 v1 = __half22float2(*(const half2*)(g_h2 + i1 * F2 + fo));
        float2 v2 = __half22float2(*(const half2*)(g_h2 + i2 * F2 + fo));
        float2 v3 = __half22float2(*(const half2*)(g_h2 + i3 * F2 + fo));
        acc.x += (v0.x + v1.x) + (v2.x + v3.x);
        acc.y += (v0.y + v1.y) + (v2.y + v3.y);
    }
    for (; j < end; j++) {
        float2 v0 = __half22float2(*(const half2*)(g_h2 + g_csr[j] * F2 + fo));
        acc.x += v0.x; acc.y += v0.y;
    }

    float s = g_dinv[c];
    float2 bb = *(const float2*)(b2 + fo);
    out[c * F2 + fo + 0] = fmaf(s, acc.x, bb.x);
    out[c * F2 + fo + 1] = fmaf(s, acc.y, bb.y);
}

extern "C" void kernel_launch(void* const* d_in, const int* in_sizes, int n_in,
                              void* d_out, int out_size) {
    const float* x  = (const float*)d_in[0];
    const void*  ei = d_in[1];
    const float* W1 = (const float*)d_in[2];
    const float* b1 = (const float*)d_in[3];
    const float* W2 = (const float*)d_in[4];
    const float* b2 = (const float*)d_in[5];
    float* out = (float*)d_out;

    int E = in_sizes[1] / 2;
    if (E > MAX_E) E = MAX_E;

    // One-time side stream + fork/join events (created outside graph capture).
    static cudaStream_t s_b = 0;
    static cudaEvent_t  e_fork = 0, e_join = 0;
    static int s_ok = -1;
    if (s_ok < 0) {
        s_ok = (cudaStreamCreateWithFlags(&s_b, cudaStreamNonBlocking) == cudaSuccess &&
                cudaEventCreateWithFlags(&e_fork, cudaEventDisableTiming) == cudaSuccess &&
                cudaEventCreateWithFlags(&e_join, cudaEventDisableTiming) == cudaSuccess)
                   ? 1 : 0;
    }

    k_detect<<<1, 256>>>((const long long*)ei);
    k_prep_edges<<<(E + 255) / 256, 256>>>(ei, E);
    k_scan_block<<<NB, 256>>>();   // also writes g_dinv

    if (s_ok) {
        // Fork: CSR finalization runs concurrently with GEMM1.
        cudaEventRecord(e_fork, 0);
        cudaStreamWaitEvent(s_b, e_fork, 0);
        k_scan_top<<<1, 512, 0, s_b>>>();
        k_scan_add<<<(N_NODES + 255) / 256, 256, 0, s_b>>>();
        k_fill<<<(E + 255) / 256, 256, 0, s_b>>>(E);
        cudaEventRecord(e_join, s_b);

        k_gemm1<<<(N_NODES + 127) / 128, 256>>>(x, W1);

        cudaStreamWaitEvent(0, e_join, 0);   // gather1 needs CSR
    } else {
        k_scan_top<<<1, 512>>>();
        k_scan_add<<<(N_NODES + 255) / 256, 256>>>();
        k_fill<<<(E + 255) / 256, 256>>>(E);
        k_gemm1<<<(N_NODES + 127) / 128, 256>>>(x, W1);
    }

    k_gather1<<<(N_NODES * 32 + 255) / 256, 256>>>(b1);
    k_gemm2<<<(N_NODES + 127) / 128, 256>>>(W2);
    k_gather2<<<(N_NODES * 32 + 255) / 256, 256>>>(out, b2);
}

// round 16
// speedup vs baseline: 1.9428x; 1.9428x over previous
#include <cuda_runtime.h>
#include <cuda_fp16.h>

#define N_NODES 100000
#define F0 256
#define F1 128
#define F2 64
#define MAX_E 1600000
#define NB 391   // ceil(N_NODES/256)

// Scratch (allocation-free rule: __device__ globals). 16B-aligned for vector access.
__device__ int   g_is_i32 = 0;       // sticky: same input -> same value every call
__device__ int   g_deg[N_NODES];
__device__ float g_dinv[N_NODES];
__device__ int   g_row32[MAX_E];
__device__ int   g_col32[MAX_E];
__device__ int   g_csr[MAX_E];
__device__ int   g_pref[N_NODES];
__device__ int   g_bsum[NB];
__device__ int   g_boff[NB];
__device__ int   g_rowptr[N_NODES];
__device__ int   g_fill[N_NODES];
__device__ __align__(16) __half g_h1[N_NODES * F1];
__device__ __align__(16) __half g_y1[N_NODES * F1];
__device__ __align__(16) __half g_h2[N_NODES * F2];

// ---------------- tf32 helpers ----------------

__device__ __forceinline__ unsigned f2tf32(float f) {
    unsigned u;
    asm("cvt.rna.tf32.f32 %0, %1;" : "=r"(u) : "f"(f));
    return u;
}

__device__ __forceinline__ void mma_tf32(float* c, const unsigned* a, const unsigned* b) {
    asm volatile(
        "mma.sync.aligned.m16n8k8.row.col.f32.tf32.tf32.f32 "
        "{%0,%1,%2,%3}, {%4,%5,%6,%7}, {%8,%9}, {%0,%1,%2,%3};\n"
        : "+f"(c[0]), "+f"(c[1]), "+f"(c[2]), "+f"(c[3])
        : "r"(a[0]), "r"(a[1]), "r"(a[2]), "r"(a[3]), "r"(b[0]), "r"(b[1]));
}

// ---------------- fused init: zero degrees + dtype detect ----------------

__global__ void k_init(const long long* __restrict__ ei) {
    int i = blockIdx.x * blockDim.x + threadIdx.x;
    if (i < N_NODES) g_deg[i] = 0;
    if (blockIdx.x == 0) {
        long long v = ei[threadIdx.x];
        if (v < 0 || v >= N_NODES) g_is_i32 = 1;   // sticky, deterministic
    }
}

__global__ void k_prep_edges(const void* __restrict__ eiv, int E) {
    int e = blockIdx.x * blockDim.x + threadIdx.x;
    if (e >= E) return;
    int r, c;
    if (g_is_i32) {
        const int* p = (const int*)eiv;
        r = p[e]; c = p[E + e];
    } else {
        const long long* p = (const long long*)eiv;
        r = (int)p[e]; c = (int)p[E + e];
    }
    r = min(max(r, 0), N_NODES - 1);
    c = min(max(c, 0), N_NODES - 1);
    g_row32[e] = r;
    g_col32[e] = c;
    atomicAdd(&g_deg[c], 1);
}

// ---------------- CSR build (dinv fused into block scan) ----------------

__global__ void k_scan_block() {
    __shared__ int s[256];
    int tid = threadIdx.x;
    int i = blockIdx.x * 256 + tid;
    int v = (i < N_NODES) ? g_deg[i] : 0;
    if (i < N_NODES) g_dinv[i] = rsqrtf((float)(v + 1));
    s[tid] = v;
    __syncthreads();
#pragma unroll
    for (int d = 1; d < 256; d <<= 1) {
        int t = (tid >= d) ? s[tid - d] : 0;
        __syncthreads();
        s[tid] += t;
        __syncthreads();
    }
    if (i < N_NODES) g_pref[i] = s[tid] - v;
    if (tid == 255) g_bsum[blockIdx.x] = s[255];
}

__global__ void k_scan_top() {
    __shared__ int s[512];
    int tid = threadIdx.x;
    int v = (tid < NB) ? g_bsum[tid] : 0;
    s[tid] = v;
    __syncthreads();
#pragma unroll
    for (int d = 1; d < 512; d <<= 1) {
        int t = (tid >= d) ? s[tid - d] : 0;
        __syncthreads();
        s[tid] += t;
        __syncthreads();
    }
    if (tid < NB) g_boff[tid] = s[tid] - v;
}

__global__ void k_scan_add() {
    int i = blockIdx.x * blockDim.x + threadIdx.x;
    if (i < N_NODES) {
        int rp = g_pref[i] + g_boff[i >> 8];
        g_rowptr[i] = rp;
        g_fill[i] = rp;
    }
}

__global__ void k_fill(int E) {
    int e = blockIdx.x * blockDim.x + threadIdx.x;
    if (e >= E) return;
    int c = g_col32[e];
    int pos = atomicAdd(&g_fill[c], 1);
    g_csr[pos] = g_row32[e];
}

// ---------------- GEMM1 (tf32 mma): g_h1 = fp16( (x @ W1) * dinv[row] )

__global__ void __launch_bounds__(256) k_gemm1(const float* __restrict__ x,
                                               const float* __restrict__ W) {
    __shared__ unsigned As[128][36];
    __shared__ unsigned Bs[32][132];
    int tid = threadIdx.x;
    int lane = tid & 31;
    int wid = tid >> 5;
    int warp_m = wid & 3;
    int warp_n = wid >> 2;
    int grp = lane >> 2;
    int thr = lane & 3;
    int mbase = blockIdx.x * 128;

    float acc[2][8][4];
#pragma unroll
    for (int mf = 0; mf < 2; mf++)
#pragma unroll
        for (int nf = 0; nf < 8; nf++)
#pragma unroll
            for (int q = 0; q < 4; q++) acc[mf][nf][q] = 0.f;

    for (int kt = 0; kt < F0; kt += 32) {
#pragma unroll
        for (int i = 0; i < 4; i++) {
            int idx4 = tid + i * 256;
            int m = idx4 >> 3;
            int kk = (idx4 & 7) * 4;
            int gm = mbase + m;
            float4 v = make_float4(0.f, 0.f, 0.f, 0.f);
            if (gm < N_NODES) v = *(const float4*)(x + gm * F0 + kt + kk);
            uint4 u;
            u.x = f2tf32(v.x); u.y = f2tf32(v.y); u.z = f2tf32(v.z); u.w = f2tf32(v.w);
            *(uint4*)(&As[m][kk]) = u;
        }
#pragma unroll
        for (int i = 0; i < 4; i++) {
            int idx4 = tid + i * 256;
            int k = idx4 >> 5;
            int nn = (idx4 & 31) * 4;
            float4 v = *(const float4*)(W + (kt + k) * F1 + nn);
            uint4 u;
            u.x = f2tf32(v.x); u.y = f2tf32(v.y); u.z = f2tf32(v.z); u.w = f2tf32(v.w);
            *(uint4*)(&Bs[k][nn]) = u;
        }
        __syncthreads();

#pragma unroll
        for (int k0 = 0; k0 < 32; k0 += 8) {
            unsigned a[2][4];
#pragma unroll
            for (int mf = 0; mf < 2; mf++) {
                int r = warp_m * 32 + mf * 16 + grp;
                a[mf][0] = As[r][k0 + thr];
                a[mf][1] = As[r + 8][k0 + thr];
                a[mf][2] = As[r][k0 + 4 + thr];
                a[mf][3] = As[r + 8][k0 + 4 + thr];
            }
            unsigned b[8][2];
#pragma unroll
            for (int nf = 0; nf < 8; nf++) {
                int cNo = warp_n * 64 + nf * 8 + grp;
                b[nf][0] = Bs[k0 + thr][cNo];
                b[nf][1] = Bs[k0 + 4 + thr][cNo];
            }
#pragma unroll
            for (int mf = 0; mf < 2; mf++)
#pragma unroll
                for (int nf = 0; nf < 8; nf++)
                    mma_tf32(acc[mf][nf], a[mf], b[nf]);
        }
        __syncthreads();
    }

#pragma unroll
    for (int mf = 0; mf < 2; mf++) {
        int r0 = mbase + warp_m * 32 + mf * 16 + grp;
        int r1 = r0 + 8;
        float s0 = (r0 < N_NODES) ? g_dinv[r0] : 0.f;
        float s1 = (r1 < N_NODES) ? g_dinv[r1] : 0.f;
#pragma unroll
        for (int nf = 0; nf < 8; nf++) {
            int cNo = warp_n * 64 + nf * 8 + thr * 2;
            if (r0 < N_NODES)
                *(half2*)(g_h1 + r0 * F1 + cNo) =
                    __floats2half2_rn(acc[mf][nf][0] * s0, acc[mf][nf][1] * s0);
            if (r1 < N_NODES)
                *(half2*)(g_h1 + r1 * F1 + cNo) =
                    __floats2half2_rn(acc[mf][nf][2] * s1, acc[mf][nf][3] * s1);
        }
    }
}

// ---------------- Gather layer 1: warp per node, 4-way unroll

__global__ void __launch_bounds__(256) k_gather1(const float* __restrict__ b1) {
    int w = (blockIdx.x * blockDim.x + threadIdx.x) >> 5;
    if (w >= N_NODES) return;
    int lane = threadIdx.x & 31;
    int c = w;
    int fo = lane * 4;

    float2 a0 = __half22float2(*(const half2*)(g_h1 + c * F1 + fo));
    float2 a1 = __half22float2(*(const half2*)(g_h1 + c * F1 + fo + 2));
    float4 acc = make_float4(a0.x, a0.y, a1.x, a1.y);   // self-loop term

    int start = g_rowptr[c];
    int end = start + g_deg[c];

    int j = start;
    for (; j + 4 <= end; j += 4) {
        int i0 = g_csr[j], i1 = g_csr[j + 1], i2 = g_csr[j + 2], i3 = g_csr[j + 3];
        uint2 u0 = *(const uint2*)(g_h1 + i0 * F1 + fo);
        uint2 u1 = *(const uint2*)(g_h1 + i1 * F1 + fo);
        uint2 u2 = *(const uint2*)(g_h1 + i2 * F1 + fo);
        uint2 u3 = *(const uint2*)(g_h1 + i3 * F1 + fo);
        float2 p;
        p = __half22float2(*(half2*)&u0.x); acc.x += p.x; acc.y += p.y;
        p = __half22float2(*(half2*)&u0.y); acc.z += p.x; acc.w += p.y;
        p = __half22float2(*(half2*)&u1.x); acc.x += p.x; acc.y += p.y;
        p = __half22float2(*(half2*)&u1.y); acc.z += p.x; acc.w += p.y;
        p = __half22float2(*(half2*)&u2.x); acc.x += p.x; acc.y += p.y;
        p = __half22float2(*(half2*)&u2.y); acc.z += p.x; acc.w += p.y;
        p = __half22float2(*(half2*)&u3.x); acc.x += p.x; acc.y += p.y;
        p = __half22float2(*(half2*)&u3.y); acc.z += p.x; acc.w += p.y;
    }
    for (; j < end; j++) {
        int i0 = g_csr[j];
        uint2 u0 = *(const uint2*)(g_h1 + i0 * F1 + fo);
        float2 p;
        p = __half22float2(*(half2*)&u0.x); acc.x += p.x; acc.y += p.y;
        p = __half22float2(*(half2*)&u0.y); acc.z += p.x; acc.w += p.y;
    }

    float s = g_dinv[c];
    float4 bb = *(const float4*)(b1 + fo);
    acc.x = fmaxf(fmaf(s, acc.x, bb.x), 0.f);
    acc.y = fmaxf(fmaf(s, acc.y, bb.y), 0.f);
    acc.z = fmaxf(fmaf(s, acc.z, bb.z), 0.f);
    acc.w = fmaxf(fmaf(s, acc.w, bb.w), 0.f);
    *(half2*)(g_y1 + c * F1 + fo)     = __floats2half2_rn(acc.x, acc.y);
    *(half2*)(g_y1 + c * F1 + fo + 2) = __floats2half2_rn(acc.z, acc.w);
}

// ---------------- GEMM2 (tf32 mma): g_h2 = fp16( (y1 @ W2) * dinv[row] )

__global__ void __launch_bounds__(256) k_gemm2(const float* __restrict__ W) {
    __shared__ unsigned As[128][36];
    __shared__ unsigned Bs[32][68];
    int tid = threadIdx.x;
    int lane = tid & 31;
    int wid = tid >> 5;
    int grp = lane >> 2;
    int thr = lane & 3;
    int mbase = blockIdx.x * 128;

    float acc[8][4];
#pragma unroll
    for (int nf = 0; nf < 8; nf++)
#pragma unroll
        for (int q = 0; q < 4; q++) acc[nf][q] = 0.f;

    for (int kt = 0; kt < F1; kt += 32) {
#pragma unroll
        for (int i = 0; i < 4; i++) {
            int idx4 = tid + i * 256;
            int m = idx4 >> 3;
            int kk = (idx4 & 7) * 4;
            int gm = mbase + m;
            float2 p0 = make_float2(0.f, 0.f), p1 = make_float2(0.f, 0.f);
            if (gm < N_NODES) {
                uint2 u = *(const uint2*)(g_y1 + gm * F1 + kt + kk);
                p0 = __half22float2(*(half2*)&u.x);
                p1 = __half22float2(*(half2*)&u.y);
            }
            uint4 t;
            t.x = f2tf32(p0.x); t.y = f2tf32(p0.y); t.z = f2tf32(p1.x); t.w = f2tf32(p1.y);
            *(uint4*)(&As[m][kk]) = t;
        }
#pragma unroll
        for (int i = 0; i < 2; i++) {
            int idx4 = tid + i * 256;
            int k = idx4 >> 4;
            int nn = (idx4 & 15) * 4;
            float4 v = *(const float4*)(W + (kt + k) * F2 + nn);
            uint4 u;
            u.x = f2tf32(v.x); u.y = f2tf32(v.y); u.z = f2tf32(v.z); u.w = f2tf32(v.w);
            *(uint4*)(&Bs[k][nn]) = u;
        }
        __syncthreads();

#pragma unroll
        for (int k0 = 0; k0 < 32; k0 += 8) {
            unsigned a[4];
            int r = wid * 16 + grp;
            a[0] = As[r][k0 + thr];
            a[1] = As[r + 8][k0 + thr];
            a[2] = As[r][k0 + 4 + thr];
            a[3] = As[r + 8][k0 + 4 + thr];
            unsigned b[8][2];
#pragma unroll
            for (int nf = 0; nf < 8; nf++) {
                int cNo = nf * 8 + grp;
                b[nf][0] = Bs[k0 + thr][cNo];
                b[nf][1] = Bs[k0 + 4 + thr][cNo];
            }
#pragma unroll
            for (int nf = 0; nf < 8; nf++)
                mma_tf32(acc[nf], a, b[nf]);
        }
        __syncthreads();
    }

    int r0 = mbase + wid * 16 + grp;
    int r1 = r0 + 8;
    float s0 = (r0 < N_NODES) ? g_dinv[r0] : 0.f;
    float s1 = (r1 < N_NODES) ? g_dinv[r1] : 0.f;
#pragma unroll
    for (int nf = 0; nf < 8; nf++) {
        int cNo = nf * 8 + thr * 2;
        if (r0 < N_NODES)
            *(half2*)(g_h2 + r0 * F2 + cNo) =
                __floats2half2_rn(acc[nf][0] * s0, acc[nf][1] * s0);
        if (r1 < N_NODES)
            *(half2*)(g_h2 + r1 * F2 + cNo) =
                __floats2half2_rn(acc[nf][2] * s1, acc[nf][3] * s1);
    }
}

// ---------------- Gather layer 2: warp per node, 4-way unroll

__global__ void __launch_bounds__(256) k_gather2(float* __restrict__ out,
                                                 const float* __restrict__ b2) {
    int w = (blockIdx.x * blockDim.x + threadIdx.x) >> 5;
    if (w >= N_NODES) return;
    int lane = threadIdx.x & 31;
    int c = w;
    int fo = lane * 2;

    float2 acc = __half22float2(*(const half2*)(g_h2 + c * F2 + fo));
    int start = g_rowptr[c];
    int end = start + g_deg[c];

    int j = start;
    for (; j + 4 <= end; j += 4) {
        int i0 = g_csr[j], i1 = g_csr[j + 1], i2 = g_csr[j + 2], i3 = g_csr[j + 3];
        float2 v0 = __half22float2(*(const half2*)(g_h2 + i0 * F2 + fo));
        float2 v1 = __half22float2(*(const half2*)(g_h2 + i1 * F2 + fo));
        float2 v2 = __half22float2(*(const half2*)(g_h2 + i2 * F2 + fo));
        float2 v3 = __half22float2(*(const half2*)(g_h2 + i3 * F2 + fo));
        acc.x += (v0.x + v1.x) + (v2.x + v3.x);
        acc.y += (v0.y + v1.y) + (v2.y + v3.y);
    }
    for (; j < end; j++) {
        float2 v0 = __half22float2(*(const half2*)(g_h2 + g_csr[j] * F2 + fo));
        acc.x += v0.x; acc.y += v0.y;
    }

    float s = g_dinv[c];
    float2 bb = *(const float2*)(b2 + fo);
    out[c * F2 + fo + 0] = fmaf(s, acc.x, bb.x);
    out[c * F2 + fo + 1] = fmaf(s, acc.y, bb.y);
}

extern "C" void kernel_launch(void* const* d_in, const int* in_sizes, int n_in,
                              void* d_out, int out_size) {
    const float* x  = (const float*)d_in[0];
    const void*  ei = d_in[1];
    const float* W1 = (const float*)d_in[2];
    const float* b1 = (const float*)d_in[3];
    const float* W2 = (const float*)d_in[4];
    const float* b2 = (const float*)d_in[5];
    float* out = (float*)d_out;

    int E = in_sizes[1] / 2;
    if (E > MAX_E) E = MAX_E;

    // One-time side stream + fork/join events (created outside graph capture).
    static cudaStream_t s_b = 0;
    static cudaEvent_t  e_fork = 0, e_join = 0;
    static int s_ok = -1;
    if (s_ok < 0) {
        s_ok = (cudaStreamCreateWithFlags(&s_b, cudaStreamNonBlocking) == cudaSuccess &&
                cudaEventCreateWithFlags(&e_fork, cudaEventDisableTiming) == cudaSuccess &&
                cudaEventCreateWithFlags(&e_join, cudaEventDisableTiming) == cudaSuccess)
                   ? 1 : 0;
    }

    k_init<<<(N_NODES + 255) / 256, 256>>>((const long long*)ei);
    k_prep_edges<<<(E + 255) / 256, 256>>>(ei, E);
    k_scan_block<<<NB, 256>>>();   // also writes g_dinv

    if (s_ok) {
        // Fork: CSR finalization runs concurrently with GEMM1.
        cudaEventRecord(e_fork, 0);
        cudaStreamWaitEvent(s_b, e_fork, 0);
        k_scan_top<<<1, 512, 0, s_b>>>();
        k_scan_add<<<(N_NODES + 255) / 256, 256, 0, s_b>>>();
        k_fill<<<(E + 255) / 256, 256, 0, s_b>>>(E);
        cudaEventRecord(e_join, s_b);

        k_gemm1<<<(N_NODES + 127) / 128, 256>>>(x, W1);

        cudaStreamWaitEvent(0, e_join, 0);   // gather1 needs CSR
    } else {
        k_scan_top<<<1, 512>>>();
        k_scan_add<<<(N_NODES + 255) / 256, 256>>>();
        k_fill<<<(E + 255) / 256, 256>>>(E);
        k_gemm1<<<(N_NODES + 127) / 128, 256>>>(x, W1);
    }

    k_gather1<<<(N_NODES * 32 + 255) / 256, 256>>>(b1);
    k_gemm2<<<(N_NODES + 127) / 128, 256>>>(W2);
    k_gather2<<<(N_NODES * 32 + 255) / 256, 256>>>(out, b2);
}